// round 17
// baseline (speedup 1.0000x reference)
#include <cuda_runtime.h>
#include <cuda_bf16.h>
#include <cstdint>

#define BB 4
#define TT 2048
#define CC 1024
#define HH 16
#define DD 64
#define NTOK (BB*TT)   // 8192
#define NELEM ((size_t)NTOK*CC)   // 8388608 == BB*HH*TT*DD

// Persistent bf16 hi/lo scratch (device globals; no allocation)
__device__ __align__(16) uint16_t g_xh[NELEM], g_xl[NELEM];
__device__ __align__(16) uint16_t g_wh[(size_t)4*CC*CC], g_wl[(size_t)4*CC*CC];
__device__ __align__(16) uint16_t g_qh[NELEM], g_ql[NELEM];
__device__ __align__(16) uint16_t g_kh[NELEM], g_kl[NELEM];
__device__ __align__(16) uint16_t g_vh[NELEM], g_vl[NELEM];
__device__ __align__(16) uint16_t g_yh[NELEM], g_yl[NELEM];

// ---------------------------------------------------------------------------
// helpers (sm_80-era PTX: valid at compute_103 base target)
// ---------------------------------------------------------------------------
__device__ __forceinline__ uint32_t smem_u32(const void* p) {
    return (uint32_t)__cvta_generic_to_shared(p);
}

__device__ __forceinline__ void ldsm4(uint32_t* r, uint32_t addr) {
    asm volatile("ldmatrix.sync.aligned.m8n8.x4.shared.b16 {%0,%1,%2,%3}, [%4];"
                 : "=r"(r[0]), "=r"(r[1]), "=r"(r[2]), "=r"(r[3]) : "r"(addr));
}

__device__ __forceinline__ void ldsm4t(uint32_t* r, uint32_t addr) {
    asm volatile("ldmatrix.sync.aligned.m8n8.x4.trans.shared.b16 {%0,%1,%2,%3}, [%4];"
                 : "=r"(r[0]), "=r"(r[1]), "=r"(r[2]), "=r"(r[3]) : "r"(addr));
}

// NOTE: non-volatile on purpose — pure register op; lets nvcc/ptxas interleave
// MMAs to hide tensor-pipe latency (CUTLASS does the same).
__device__ __forceinline__ void mma_bf16(float* d, const uint32_t* a, const uint32_t* b) {
    asm("mma.sync.aligned.m16n8k16.row.col.f32.bf16.bf16.f32 "
        "{%0,%1,%2,%3}, {%4,%5,%6,%7}, {%8,%9}, {%0,%1,%2,%3};"
        : "+f"(d[0]), "+f"(d[1]), "+f"(d[2]), "+f"(d[3])
        : "r"(a[0]), "r"(a[1]), "r"(a[2]), "r"(a[3]), "r"(b[0]), "r"(b[1]));
}

__device__ __forceinline__ void split2(float x, float y, uint32_t& hp, uint32_t& lp) {
    uint32_t ux = __float_as_uint(x), uy = __float_as_uint(y);
    hp = __byte_perm(ux, uy, 0x7632);
    float lx = x - __uint_as_float(ux & 0xFFFF0000u);
    float ly = y - __uint_as_float(uy & 0xFFFF0000u);
    __nv_bfloat162 pl = __floats2bfloat162_rn(lx, ly);
    lp = *reinterpret_cast<uint32_t*>(&pl);
}

#define CP_ASYNC16(dst, src) \
    asm volatile("cp.async.cg.shared.global [%0], [%1], 16;" :: "r"(dst), "l"(src))
#define CP_COMMIT asm volatile("cp.async.commit_group;")
#define CP_WAIT0 asm volatile("cp.async.wait_group 0;")
#define CP_WAIT1 asm volatile("cp.async.wait_group 1;")

// ---------------------------------------------------------------------------
// Pre-split pass: fp32 -> bf16 hi/lo (x in one launch, 4 weights in one)
// ---------------------------------------------------------------------------
__global__ __launch_bounds__(256) void split_x_kernel(const float* __restrict__ src, int n4)
{
    int i = blockIdx.x * blockDim.x + threadIdx.x;
    if (i >= n4) return;
    float4 v = ((const float4*)src)[i];
    uint32_t h01, l01, h23, l23;
    split2(v.x, v.y, h01, l01);
    split2(v.z, v.w, h23, l23);
    ((uint2*)g_xh)[i] = make_uint2(h01, h23);
    ((uint2*)g_xl)[i] = make_uint2(l01, l23);
}

__global__ __launch_bounds__(256) void split_w_kernel(
    const float* __restrict__ w0, const float* __restrict__ w1,
    const float* __restrict__ w2, const float* __restrict__ w3)
{
    const int per = CC * CC / 4;   // float4s per weight
    int i = blockIdx.x * blockDim.x + threadIdx.x;
    const int slot = i / per;
    const int j = i - slot * per;
    const float* src = (slot == 0) ? w0 : (slot == 1) ? w1 : (slot == 2) ? w2 : w3;
    float4 v = ((const float4*)src)[j];
    uint32_t h01, l01, h23, l23;
    split2(v.x, v.y, h01, l01);
    split2(v.z, v.w, h23, l23);
    ((uint2*)g_wh)[i] = make_uint2(h01, h23);
    ((uint2*)g_wl)[i] = make_uint2(l01, l23);
}

// ---------------------------------------------------------------------------
// HMMA GEMM: out[n][o] = sum_c A[n][c]*W[o][c] + bias[o]
// cp.async 3-stage pipeline, BK=32, XOR-swizzled 64B rows.
// MMAs emitted in 3 term-passes (16 independent accumulators per pass).
// ---------------------------------------------------------------------------
#define BKC 32
#define NCH (CC / BKC)           // 32
#define GS_TILE 8192             // 128 * 64B
#define GS_STAGE (4 * GS_TILE)   // 32768
#define G_SMEM (3 * GS_STAGE)    // 98304

__global__ __launch_bounds__(256) void mma_linear(
    int asel, int wsel, const float* __restrict__ bias,
    float* __restrict__ out_ext, int dst_sel)
{
    extern __shared__ __align__(128) char smem[];
    const uint32_t sb = smem_u32(smem);
    const int tid = threadIdx.x;
    const int wid = tid >> 5;
    const int lane = tid & 31;
    const int n0 = blockIdx.x * 128;
    const int o0 = blockIdx.y * 128;

    const uint16_t* __restrict__ Ah = asel ? g_yh : g_xh;
    const uint16_t* __restrict__ Al = asel ? g_yl : g_xl;
    const uint16_t* __restrict__ Wh = g_wh + (size_t)wsel * CC * CC;
    const uint16_t* __restrict__ Wl = g_wl + (size_t)wsel * CC * CC;

    const int wm = (wid >> 1) * 32;
    const int wn = (wid & 1) * 64;
    const int ar  = wm + (lane & 15);
    const int ak  = (lane >> 4);
    const int bn  = wn + ((lane >> 4) & 1) * 8 + (lane & 7);
    const int bk  = ((lane >> 3) & 1);

    float acc[2][8][4];
#pragma unroll
    for (int mf = 0; mf < 2; mf++)
#pragma unroll
        for (int nf = 0; nf < 8; nf++)
#pragma unroll
            for (int e = 0; e < 4; e++) acc[mf][nf][e] = 0.f;

#define G_ISSUE(i, s) do {                                                     \
    const int _k0 = (i) * BKC;                                                 \
    const uint32_t _stb = sb + (uint32_t)(s) * GS_STAGE;                       \
    _Pragma("unroll")                                                          \
    for (int t = 0; t < 8; t++) {                                              \
        const int tile = t >> 1;                                               \
        const int idx2 = tid + (t & 1) * 256;                                  \
        const int row = idx2 >> 2, cc = idx2 & 3;                              \
        const uint32_t dst = _stb + tile * GS_TILE + row * 64                  \
                             + ((cc ^ ((row >> 1) & 3)) << 4);                 \
        const uint16_t* srcp;                                                  \
        if (tile == 0)      srcp = Ah + (size_t)(n0 + row) * CC + _k0 + cc * 8;\
        else if (tile == 1) srcp = Al + (size_t)(n0 + row) * CC + _k0 + cc * 8;\
        else if (tile == 2) srcp = Wh + (size_t)(o0 + row) * CC + _k0 + cc * 8;\
        else                srcp = Wl + (size_t)(o0 + row) * CC + _k0 + cc * 8;\
        CP_ASYNC16(dst, srcp);                                                 \
    }                                                                          \
    CP_COMMIT;                                                                 \
} while (0)

#define G_COMPUTE(stagebase) do {                                              \
    _Pragma("unroll")                                                          \
    for (int kk = 0; kk < 2; kk++) {                                           \
        uint32_t ah[2][4], al[2][4], bh2[4][4], bl2[4][4];                     \
        _Pragma("unroll")                                                      \
        for (int mf = 0; mf < 2; mf++) {                                       \
            const int r = ar + mf * 16;                                        \
            const int c = kk * 2 + ak;                                         \
            const uint32_t aoff = (uint32_t)(r * 64 + ((c ^ ((r >> 1) & 3)) << 4)); \
            ldsm4(ah[mf], (stagebase) + aoff);                                 \
            ldsm4(al[mf], (stagebase) + GS_TILE + aoff);                       \
        }                                                                      \
        _Pragma("unroll")                                                      \
        for (int p = 0; p < 4; p++) {                                          \
            const int r = bn + p * 16;                                         \
            const int c = kk * 2 + bk;                                         \
            const uint32_t boff = (uint32_t)(r * 64 + ((c ^ ((r >> 1) & 3)) << 4)); \
            ldsm4(bh2[p], (stagebase) + 2 * GS_TILE + boff);                   \
            ldsm4(bl2[p], (stagebase) + 3 * GS_TILE + boff);                   \
        }                                                                      \
        /* pass 1: Ah*Bh — 16 independent accumulators */                      \
        _Pragma("unroll")                                                      \
        for (int mf = 0; mf < 2; mf++)                                         \
            _Pragma("unroll")                                                  \
            for (int p = 0; p < 4; p++) {                                      \
                mma_bf16(acc[mf][2*p],   ah[mf], &bh2[p][0]);                  \
                mma_bf16(acc[mf][2*p+1], ah[mf], &bh2[p][2]);                  \
            }                                                                  \
        /* pass 2: Al*Bh */                                                    \
        _Pragma("unroll")                                                      \
        for (int mf = 0; mf < 2; mf++)                                         \
            _Pragma("unroll")                                                  \
            for (int p = 0; p < 4; p++) {                                      \
                mma_bf16(acc[mf][2*p],   al[mf], &bh2[p][0]);                  \
                mma_bf16(acc[mf][2*p+1], al[mf], &bh2[p][2]);                  \
            }                                                                  \
        /* pass 3: Ah*Bl */                                                    \
        _Pragma("unroll")                                                      \
        for (int mf = 0; mf < 2; mf++)                                         \
            _Pragma("unroll")                                                  \
            for (int p = 0; p < 4; p++) {                                      \
                mma_bf16(acc[mf][2*p],   ah[mf], &bl2[p][0]);                  \
                mma_bf16(acc[mf][2*p+1], ah[mf], &bl2[p][2]);                  \
            }                                                                  \
    }                                                                          \
} while (0)

    G_ISSUE(0, 0);
    G_ISSUE(1, 1);

    for (int i = 0; i < NCH; i++) {
        if (i == NCH - 1) { CP_WAIT0; } else { CP_WAIT1; }
        __syncthreads();
        if (i + 2 < NCH) {
            const int s2 = (i + 2) % 3;
            G_ISSUE(i + 2, s2);
        }
        G_COMPUTE(sb + (uint32_t)(i % 3) * GS_STAGE);
    }

    // epilogue
    const int g = lane >> 2;
    const int tg = lane & 3;
#pragma unroll
    for (int mf = 0; mf < 2; mf++) {
#pragma unroll
        for (int nf = 0; nf < 8; nf++) {
            const int col = o0 + wn + nf * 8 + tg * 2;
            const float b0 = __ldg(&bias[col]);
            const float b1 = __ldg(&bias[col + 1]);
#pragma unroll
            for (int hrow = 0; hrow < 2; hrow++) {
                const int n = n0 + wm + mf * 16 + g + hrow * 8;
                float v0 = acc[mf][nf][hrow * 2 + 0] + b0;
                float v1 = acc[mf][nf][hrow * 2 + 1] + b1;
                if (dst_sel == 3) {
                    *(float2*)(out_ext + (size_t)n * CC + col) = make_float2(v0, v1);
                } else {
                    if (dst_sel == 0) { v0 *= 0.125f; v1 *= 0.125f; }
                    uint32_t hp, lp;
                    split2(v0, v1, hp, lp);
                    const int b = n >> 11, t = n & (TT - 1);
                    const int h = col >> 6, d = col & 63;
                    const size_t idx = (((size_t)(b * HH + h) * TT + t) << 6) + d;
                    uint16_t* dsth = (dst_sel == 0) ? g_qh : (dst_sel == 1) ? g_kh : g_vh;
                    uint16_t* dstl = (dst_sel == 0) ? g_ql : (dst_sel == 1) ? g_kl : g_vl;
                    *(uint32_t*)(dsth + idx) = hp;
                    *(uint32_t*)(dstl + idx) = lp;
                }
            }
        }
    }
#undef G_ISSUE
#undef G_COMPUTE
}

// ---------------------------------------------------------------------------
// HMMA flash attention v4, causal. CTA = 64 queries of one (b,h), 4 warps,
// 128 threads, 3 CTAs/SM (smem 64KB). 128B XOR-swizzled rows (cc ^ (row&7)).
// Q staged into stage-1's buffer. QK^T MMAs emitted in 3 term-passes.
// ---------------------------------------------------------------------------
#define AKV_TILE 8192                 // 64 rows x 128B
#define A_STAGE (4 * AKV_TILE)        // 32768
#define A_SMEM (2 * A_STAGE)          // 65536

__global__ __launch_bounds__(128, 3) void attn_kernel()
{
    extern __shared__ __align__(128) char smem[];
    const uint32_t sb = smem_u32(smem);
    const int tid = threadIdx.x;
    const int wid = tid >> 5;
    const int lane = tid & 31;
    const int qi = gridDim.x - 1 - blockIdx.x;   // heavy tiles first
    const int bh = blockIdx.y;
    const int q0 = qi * 64;
    const size_t bhbase = (size_t)bh * TT;

    const int ar  = wid * 16 + (lane & 15);
    const int ac  = (lane >> 4);
    const int bn  = ((lane >> 4) & 1) * 8 + (lane & 7);
    const int bc  = ((lane >> 3) & 1);
    const int vrow = lane & 15;
    const int vc   = (lane >> 4);

#define A_ISSUE_Q do {                                                         \
    const uint32_t _qb = sb + A_STAGE;  /* stage-1 space */                    \
    _Pragma("unroll")                                                          \
    for (int t = 0; t < 8; t++) {                                              \
        const int idx2 = tid + t * 128;                                        \
        const int tile = idx2 >> 9;                                            \
        const int row = (idx2 >> 3) & 63, cc = idx2 & 7;                       \
        const uint32_t dst = _qb + tile * AKV_TILE + row * 128                 \
                             + ((cc ^ (row & 7)) << 4);                        \
        const uint16_t* srcp = (tile ? g_ql : g_qh)                            \
                               + ((bhbase + q0 + row) << 6) + cc * 8;          \
        CP_ASYNC16(dst, srcp);                                                 \
    }                                                                          \
    CP_COMMIT;                                                                 \
} while (0)

#define A_ISSUE_KV(kt, s) do {                                                 \
    const int _k0 = (kt) * 64;                                                 \
    const uint32_t _stb = sb + (uint32_t)(s) * A_STAGE;                        \
    _Pragma("unroll")                                                          \
    for (int t = 0; t < 16; t++) {                                             \
        const int idx2 = tid + t * 128;                                        \
        const int tile = idx2 >> 9;                                            \
        const int row = (idx2 >> 3) & 63, cc = idx2 & 7;                       \
        const uint32_t dst = _stb + tile * AKV_TILE + row * 128                \
                             + ((cc ^ (row & 7)) << 4);                        \
        const uint16_t* srcp;                                                  \
        if (tile == 0)      srcp = g_kh + ((bhbase + _k0 + row) << 6) + cc * 8;\
        else if (tile == 1) srcp = g_kl + ((bhbase + _k0 + row) << 6) + cc * 8;\
        else if (tile == 2) srcp = g_vh + ((bhbase + _k0 + row) << 6) + cc * 8;\
        else                srcp = g_vl + ((bhbase + _k0 + row) << 6) + cc * 8;\
        CP_ASYNC16(dst, srcp);                                                 \
    }                                                                          \
    CP_COMMIT;                                                                 \
} while (0)

    A_ISSUE_Q;
    A_ISSUE_KV(0, 0);
    CP_WAIT1;            // Q arrived
    __syncthreads();

    uint32_t qh[4][4], ql[4][4];
    {
        const uint32_t qb = sb + A_STAGE;
#pragma unroll
        for (int kk = 0; kk < 4; kk++) {
            const int cch = 2 * kk + ac;
            const uint32_t aoff = (uint32_t)(ar * 128 + ((cch ^ (ar & 7)) << 4));
            ldsm4(qh[kk], qb + aoff);
            ldsm4(ql[kk], qb + AKV_TILE + aoff);
        }
    }

    float o[8][4];
#pragma unroll
    for (int nf = 0; nf < 8; nf++)
#pragma unroll
        for (int e = 0; e < 4; e++) o[nf][e] = 0.f;
    float m0 = -1e30f, m1 = -1e30f, l0 = 0.f, l1 = 0.f;

    const int r0 = lane >> 2;
    const int c0 = (lane & 3) * 2;

    for (int kt = 0; kt <= qi; kt++) {
        CP_WAIT0;
        __syncthreads();
        if (kt < qi) A_ISSUE_KV(kt + 1, (kt + 1) & 1);

        const uint32_t st = sb + (uint32_t)(kt & 1) * A_STAGE;

        // ---- S = Q K^T (3 term-passes, 8 independent accs per pass) ----
        float s[8][4];
#pragma unroll
        for (int nf = 0; nf < 8; nf++)
#pragma unroll
            for (int e = 0; e < 4; e++) s[nf][e] = 0.f;

#pragma unroll
        for (int kk = 0; kk < 4; kk++) {
            uint32_t kh[4][4], kl[4][4];
#pragma unroll
            for (int p = 0; p < 4; p++) {
                const int r = bn + p * 16;
                const int cch = 2 * kk + bc;
                const uint32_t boff = (uint32_t)(r * 128 + ((cch ^ (r & 7)) << 4));
                ldsm4(kh[p], st + boff);
                ldsm4(kl[p], st + AKV_TILE + boff);
            }
#pragma unroll
            for (int p = 0; p < 4; p++) {
                mma_bf16(s[2*p],   qh[kk], &kh[p][0]);
                mma_bf16(s[2*p+1], qh[kk], &kh[p][2]);
            }
#pragma unroll
            for (int p = 0; p < 4; p++) {
                mma_bf16(s[2*p],   ql[kk], &kh[p][0]);
                mma_bf16(s[2*p+1], ql[kk], &kh[p][2]);
            }
#pragma unroll
            for (int p = 0; p < 4; p++) {
                mma_bf16(s[2*p],   qh[kk], &kl[p][0]);
                mma_bf16(s[2*p+1], qh[kk], &kl[p][2]);
            }
        }

        // ---- causal mask (diagonal tile only) ----
        if (kt == qi) {
            const int lr0 = wid * 16 + r0;
            const int lr1 = lr0 + 8;
#pragma unroll
            for (int nf = 0; nf < 8; nf++) {
                const int lc = nf * 8 + c0;
                if (lc     > lr0) s[nf][0] = -1e30f;
                if (lc + 1 > lr0) s[nf][1] = -1e30f;
                if (lc     > lr1) s[nf][2] = -1e30f;
                if (lc + 1 > lr1) s[nf][3] = -1e30f;
            }
        }

        // ---- online softmax ----
        float mx0 = -1e30f, mx1 = -1e30f;
#pragma unroll
        for (int nf = 0; nf < 8; nf++) {
            mx0 = fmaxf(mx0, fmaxf(s[nf][0], s[nf][1]));
            mx1 = fmaxf(mx1, fmaxf(s[nf][2], s[nf][3]));
        }
        mx0 = fmaxf(mx0, __shfl_xor_sync(0xffffffffu, mx0, 1));
        mx0 = fmaxf(mx0, __shfl_xor_sync(0xffffffffu, mx0, 2));
        mx1 = fmaxf(mx1, __shfl_xor_sync(0xffffffffu, mx1, 1));
        mx1 = fmaxf(mx1, __shfl_xor_sync(0xffffffffu, mx1, 2));

        const float mn0 = fmaxf(m0, mx0);
        const float mn1 = fmaxf(m1, mx1);
        const float fac0 = __expf(m0 - mn0);
        const float fac1 = __expf(m1 - mn1);
        m0 = mn0; m1 = mn1;

        float rs0 = 0.f, rs1 = 0.f;
#pragma unroll
        for (int nf = 0; nf < 8; nf++) {
            s[nf][0] = __expf(s[nf][0] - mn0);
            s[nf][1] = __expf(s[nf][1] - mn0);
            s[nf][2] = __expf(s[nf][2] - mn1);
            s[nf][3] = __expf(s[nf][3] - mn1);
            rs0 += s[nf][0] + s[nf][1];
            rs1 += s[nf][2] + s[nf][3];
        }
        rs0 += __shfl_xor_sync(0xffffffffu, rs0, 1);
        rs0 += __shfl_xor_sync(0xffffffffu, rs0, 2);
        rs1 += __shfl_xor_sync(0xffffffffu, rs1, 1);
        rs1 += __shfl_xor_sync(0xffffffffu, rs1, 2);
        l0 = l0 * fac0 + rs0;
        l1 = l1 * fac1 + rs1;

#pragma unroll
        for (int nf = 0; nf < 8; nf++) {
            o[nf][0] *= fac0; o[nf][1] *= fac0;
            o[nf][2] *= fac1; o[nf][3] *= fac1;
        }

        // ---- O += P V (compiler now free to interleave across gg) ----
#pragma unroll
        for (int kp = 0; kp < 4; kp++) {
            uint32_t pa_h[4], pa_l[4];
            split2(s[2*kp][0],   s[2*kp][1],   pa_h[0], pa_l[0]);
            split2(s[2*kp][2],   s[2*kp][3],   pa_h[1], pa_l[1]);
            split2(s[2*kp+1][0], s[2*kp+1][1], pa_h[2], pa_l[2]);
            split2(s[2*kp+1][2], s[2*kp+1][3], pa_h[3], pa_l[3]);
#pragma unroll
            for (int gg = 0; gg < 4; gg++) {
                uint32_t vh[4], vl[4];
                const int r = kp * 16 + vrow;
                const int cch = 2 * gg + vc;
                const uint32_t voff = (uint32_t)(r * 128 + ((cch ^ (r & 7)) << 4));
                ldsm4t(vh, st + 2 * AKV_TILE + voff);
                ldsm4t(vl, st + 3 * AKV_TILE + voff);
                mma_bf16(o[2*gg],   pa_h, &vh[0]);
                mma_bf16(o[2*gg+1], pa_h, &vh[2]);
                mma_bf16(o[2*gg],   pa_l, &vh[0]);
                mma_bf16(o[2*gg+1], pa_l, &vh[2]);
                mma_bf16(o[2*gg],   pa_h, &vl[0]);
                mma_bf16(o[2*gg+1], pa_h, &vl[2]);
            }
        }
    }

    // ---- epilogue: y hi/lo bf16, y[b][t][h*64+d] ----
    const int b = bh >> 4, h = bh & 15;
    const float inv0 = 1.f / l0;
    const float inv1 = 1.f / l1;
    const int rg0 = q0 + wid * 16 + r0;
    const int rg1 = rg0 + 8;
#pragma unroll
    for (int nf = 0; nf < 8; nf++) {
        const int col = h * 64 + nf * 8 + c0;
        uint32_t hp, lp;
        split2(o[nf][0] * inv0, o[nf][1] * inv0, hp, lp);
        *(uint32_t*)(g_yh + (size_t)(b * TT + rg0) * CC + col) = hp;
        *(uint32_t*)(g_yl + (size_t)(b * TT + rg0) * CC + col) = lp;
        split2(o[nf][2] * inv1, o[nf][3] * inv1, hp, lp);
        *(uint32_t*)(g_yh + (size_t)(b * TT + rg1) * CC + col) = hp;
        *(uint32_t*)(g_yl + (size_t)(b * TT + rg1) * CC + col) = lp;
    }
#undef A_ISSUE_Q
#undef A_ISSUE_KV
}

// ---------------------------------------------------------------------------
extern "C" void kernel_launch(void* const* d_in, const int* in_sizes, int n_in,
                              void* d_out, int out_size)
{
    const float* x  = (const float*)d_in[0];
    const float* Wq = (const float*)d_in[1];
    const float* bq = (const float*)d_in[2];
    const float* Wk = (const float*)d_in[3];
    const float* bk = (const float*)d_in[4];
    const float* Wv = (const float*)d_in[5];
    const float* bv = (const float*)d_in[6];
    const float* Wp = (const float*)d_in[7];
    const float* bp = (const float*)d_in[8];
    float* out = (float*)d_out;

    cudaFuncSetAttribute(mma_linear, cudaFuncAttributeMaxDynamicSharedMemorySize, G_SMEM);
    cudaFuncSetAttribute(attn_kernel, cudaFuncAttributeMaxDynamicSharedMemorySize, A_SMEM);

    const int n4x = (int)(NELEM / 4);
    const int n4w = 4 * CC * CC / 4;
    split_x_kernel<<<n4x / 256, 256>>>(x, n4x);
    split_w_kernel<<<n4w / 256, 256>>>(Wq, Wk, Wv, Wp);

    dim3 gb(256);
    dim3 gg(NTOK / 128, CC / 128);  // 64 x 8

    mma_linear<<<gg, gb, G_SMEM>>>(0, 0, bq, nullptr, 0);
    mma_linear<<<gg, gb, G_SMEM>>>(0, 1, bk, nullptr, 1);
    mma_linear<<<gg, gb, G_SMEM>>>(0, 2, bv, nullptr, 2);

    attn_kernel<<<dim3(TT / 64, BB * HH), 128, A_SMEM>>>();

    mma_linear<<<gg, gb, G_SMEM>>>(1, 3, bp, out, 3);
}